// round 2
// baseline (speedup 1.0000x reference)
#include <cuda_runtime.h>
#include <cuda_bf16.h>
#include <cstdint>
#include <math.h>

// ============================================================
// x(1024,512) f32, prototypes(100,10,512) f32, log_dist_scales(100,10,512) f32
// out(1024,100) = logsumexp_p( -( sum_d w*(x-p)^2 ) ),  w = exp(ls)
// dist[b,cp] = [x^2, x] . [w, -2wp]^T + t3[cp]
// GEMM: M=1024, N=1024 (CP=1000 padded), K=1024, bf16 in, f32 accum
// Implemented with mma.sync.m16n8k16 (compute_100-safe; tcgen05 rejected by
// the harness's compute_100 ptxas target).
// ============================================================

#define MB 1024
#define ND 1024
#define KD 1024

#define BM 128
#define BN 64
#define BK 64
#define NKT (KD / BK)   // 16

// ---------------- device scratch ----------------
__device__ __nv_bfloat16 g_A[MB * KD];    // [b][k]  k<512: x^2, k>=512: x
__device__ __nv_bfloat16 g_Bm[ND * KD];   // [cp][k] k<512: w,   k>=512: -2wp (rows>=1000 stay 0)
__device__ float g_t3[ND];
__device__ float g_dist[MB * ND];

// ---------------- helpers ----------------
__device__ __forceinline__ uint32_t smem_u32(const void* p) {
    uint32_t a;
    asm("{ .reg .u64 t; cvta.to.shared.u64 t, %1; cvt.u32.u64 %0, t; }" : "=r"(a) : "l"(p));
    return a;
}
__device__ __forceinline__ uint32_t sw128(uint32_t off) {
    return off ^ ((off >> 3) & 0x70);
}
#define CP_ASYNC16(dst, src) \
    asm volatile("cp.async.cg.shared.global [%0], [%1], 16;" :: "r"(dst), "l"(src) : "memory")
#define CP_COMMIT() asm volatile("cp.async.commit_group;" ::: "memory")
#define CP_WAIT1()  asm volatile("cp.async.wait_group 1;" ::: "memory")
#define CP_WAIT0()  asm volatile("cp.async.wait_group 0;" ::: "memory")

#define LDMATRIX_X4(r0, r1, r2, r3, addr) \
    asm volatile("ldmatrix.sync.aligned.m8n8.x4.shared.b16 {%0,%1,%2,%3}, [%4];" \
                 : "=r"(r0), "=r"(r1), "=r"(r2), "=r"(r3) : "r"(addr))
#define LDMATRIX_X2(r0, r1, addr) \
    asm volatile("ldmatrix.sync.aligned.m8n8.x2.shared.b16 {%0,%1}, [%2];" \
                 : "=r"(r0), "=r"(r1) : "r"(addr))
#define MMA_16816(c0, c1, c2, c3, a0, a1, a2, a3, b0, b1) \
    asm volatile("mma.sync.aligned.m16n8k16.row.col.f32.bf16.bf16.f32 " \
                 "{%0,%1,%2,%3}, {%4,%5,%6,%7}, {%8,%9}, {%0,%1,%2,%3};" \
                 : "+f"(c0), "+f"(c1), "+f"(c2), "+f"(c3) \
                 : "r"(a0), "r"(a1), "r"(a2), "r"(a3), "r"(b0), "r"(b1))

// ---------------- prep kernels ----------------
__global__ void prep_x_kernel(const float* __restrict__ x) {
    int idx = blockIdx.x * blockDim.x + threadIdx.x;
    int b = idx >> 9;
    int d = idx & 511;
    float v = x[idx];
    g_A[b * KD + d]       = __float2bfloat16(v * v);
    g_A[b * KD + 512 + d] = __float2bfloat16(v);
}

__global__ void prep_proto_kernel(const float* __restrict__ proto, const float* __restrict__ ls) {
    int cp = blockIdx.x;       // 0..999
    int tid = threadIdx.x;     // 256
    float acc = 0.f;
    for (int d = tid; d < 512; d += 256) {
        float w = expf(ls[cp * 512 + d]);
        float p = proto[cp * 512 + d];
        g_Bm[cp * KD + d]       = __float2bfloat16(w);
        g_Bm[cp * KD + 512 + d] = __float2bfloat16(-2.0f * w * p);
        acc += w * p * p;
    }
    #pragma unroll
    for (int o = 16; o > 0; o >>= 1) acc += __shfl_xor_sync(0xffffffffu, acc, o);
    __shared__ float red[8];
    if ((tid & 31) == 0) red[tid >> 5] = acc;
    __syncthreads();
    if (tid == 0) {
        float s = 0.f;
        #pragma unroll
        for (int i = 0; i < 8; i++) s += red[i];
        g_t3[cp] = s;
    }
}

// ---------------- GEMM: mma.sync bf16, 128x64 tiles, cp.async double-buffer ----------------
// SMEM: A[2][128][64] bf16 (SW128, 16KB each), B[2][64][64] bf16 (8KB each) = 48KB
#define SA_OFF(buf) ((buf) * 16384)
#define SB_OFF(buf) (32768 + (buf) * 8192)

__global__ __launch_bounds__(256, 1) void gemm_kernel() {
    __shared__ __align__(1024) char smem[49152];
    const uint32_t sbase = smem_u32(smem);
    const int tid = threadIdx.x;
    const int wid = tid >> 5;
    const int lid = tid & 31;
    const int m0 = blockIdx.y * BM;
    const int n0 = blockIdx.x * BN;

    // ---- load plan: 16B chunks. A: 128 rows x 8 chunks = 1024 (4/thread); B: 64x8=512 (2/thread)
    const __nv_bfloat16* a_src[4];
    uint32_t a_dst[4];
    #pragma unroll
    for (int i = 0; i < 4; i++) {
        int q = tid + i * 256;
        int r = q >> 3, c = q & 7;
        a_src[i] = g_A + (size_t)(m0 + r) * KD + c * 8;
        a_dst[i] = sw128((uint32_t)r * 128u + (uint32_t)c * 16u);
    }
    const __nv_bfloat16* b_src[2];
    uint32_t b_dst[2];
    #pragma unroll
    for (int i = 0; i < 2; i++) {
        int q = tid + i * 256;
        int r = q >> 3, c = q & 7;
        b_src[i] = g_Bm + (size_t)(n0 + r) * KD + c * 8;
        b_dst[i] = sw128((uint32_t)r * 128u + (uint32_t)c * 16u);
    }

    // warp layout: 4 (M) x 2 (N); warp tile 32x32
    const int wm = (wid >> 1) * 32;
    const int wn = (wid & 1) * 32;

    float acc[2][4][4];
    #pragma unroll
    for (int mf = 0; mf < 2; mf++)
        #pragma unroll
        for (int nf = 0; nf < 4; nf++)
            #pragma unroll
            for (int i = 0; i < 4; i++) acc[mf][nf][i] = 0.f;

    // precompute ldmatrix lane-address components (swizzled offsets within tile)
    const int l4 = lid & 15;
    // A: row = wm + mf*16 + (lid&15), chunk = ks*2 + (lid>>4)
    // B: row = wn + nf*8 + (l4&7),    chunk = ks*2 + (l4>>3)
    uint32_t a_lm_off[2][4];   // [mf][ks]
    uint32_t b_lm_off[4][4];   // [nf][ks]
    #pragma unroll
    for (int mf = 0; mf < 2; mf++)
        #pragma unroll
        for (int ks = 0; ks < 4; ks++) {
            uint32_t r = wm + mf * 16 + (lid & 15);
            uint32_t ch = ks * 2 + (lid >> 4);
            a_lm_off[mf][ks] = sw128(r * 128u + ch * 16u);
        }
    #pragma unroll
    for (int nf = 0; nf < 4; nf++)
        #pragma unroll
        for (int ks = 0; ks < 4; ks++) {
            uint32_t r = wn + nf * 8 + (l4 & 7);
            uint32_t ch = ks * 2 + (l4 >> 3);
            b_lm_off[nf][ks] = sw128(r * 128u + ch * 16u);
        }

    // ---- prologue: load tile 0 ----
    {
        uint32_t sa = sbase + SA_OFF(0), sb = sbase + SB_OFF(0);
        #pragma unroll
        for (int i = 0; i < 4; i++) CP_ASYNC16(sa + a_dst[i], a_src[i]);
        #pragma unroll
        for (int i = 0; i < 2; i++) CP_ASYNC16(sb + b_dst[i], b_src[i]);
        CP_COMMIT();
    }

    for (int kt = 0; kt < NKT; kt++) {
        if (kt + 1 < NKT) {
            int nb = (kt + 1) & 1;
            uint32_t sa = sbase + SA_OFF(nb), sb = sbase + SB_OFF(nb);
            #pragma unroll
            for (int i = 0; i < 4; i++) CP_ASYNC16(sa + a_dst[i], a_src[i] + (kt + 1) * BK);
            #pragma unroll
            for (int i = 0; i < 2; i++) CP_ASYNC16(sb + b_dst[i], b_src[i] + (kt + 1) * BK);
            CP_COMMIT();
            CP_WAIT1();
        } else {
            CP_WAIT0();
        }
        __syncthreads();

        const uint32_t sa = sbase + SA_OFF(kt & 1);
        const uint32_t sb = sbase + SB_OFF(kt & 1);
        #pragma unroll
        for (int ks = 0; ks < 4; ks++) {
            uint32_t a[2][4], b[4][2];
            #pragma unroll
            for (int mf = 0; mf < 2; mf++)
                LDMATRIX_X4(a[mf][0], a[mf][1], a[mf][2], a[mf][3], sa + a_lm_off[mf][ks]);
            #pragma unroll
            for (int nf = 0; nf < 4; nf++)
                LDMATRIX_X2(b[nf][0], b[nf][1], sb + b_lm_off[nf][ks]);
            #pragma unroll
            for (int mf = 0; mf < 2; mf++)
                #pragma unroll
                for (int nf = 0; nf < 4; nf++)
                    MMA_16816(acc[mf][nf][0], acc[mf][nf][1], acc[mf][nf][2], acc[mf][nf][3],
                              a[mf][0], a[mf][1], a[mf][2], a[mf][3], b[nf][0], b[nf][1]);
        }
        __syncthreads();
    }

    // ---- epilogue: fp32 accum -> g_dist ----
    const int qr = lid >> 2;        // 0..7
    const int qc = (lid & 3) * 2;   // 0,2,4,6
    #pragma unroll
    for (int mf = 0; mf < 2; mf++) {
        #pragma unroll
        for (int nf = 0; nf < 4; nf++) {
            int row = m0 + wm + mf * 16 + qr;
            int col = n0 + wn + nf * 8 + qc;
            float2 v0 = make_float2(acc[mf][nf][0], acc[mf][nf][1]);
            float2 v1 = make_float2(acc[mf][nf][2], acc[mf][nf][3]);
            *reinterpret_cast<float2*>(g_dist + (size_t)row * ND + col) = v0;
            *reinterpret_cast<float2*>(g_dist + (size_t)(row + 8) * ND + col) = v1;
        }
    }
}

// ---------------- logsumexp epilogue ----------------
__global__ void lse_kernel(float* __restrict__ out) {
    int b = blockIdx.x;
    int c = threadIdx.x;
    if (c >= 100) return;
    const float* dp = g_dist + (size_t)b * ND + c * 10;
    const float* t3 = g_t3 + c * 10;
    float s[10];
    float mx = -3.4e38f;
    #pragma unroll
    for (int p = 0; p < 10; p++) {
        float v = -(dp[p] + t3[p]);
        s[p] = v;
        mx = fmaxf(mx, v);
    }
    float acc = 0.f;
    #pragma unroll
    for (int p = 0; p < 10; p++) acc += expf(s[p] - mx);
    out[b * 100 + c] = mx + logf(acc);
}

// ---------------- launch ----------------
extern "C" void kernel_launch(void* const* d_in, const int* in_sizes, int n_in,
                              void* d_out, int out_size) {
    const float* x     = (const float*)d_in[0];  // (1024, 512)
    const float* proto = (const float*)d_in[1];  // (100, 10, 512)
    const float* ls    = (const float*)d_in[2];  // (100, 10, 512)
    float* out = (float*)d_out;                  // (1024, 100)

    prep_x_kernel<<<(MB * 512) / 256, 256>>>(x);
    prep_proto_kernel<<<1000, 256>>>(proto, ls);
    gemm_kernel<<<dim3(ND / BN, MB / BM), 256>>>();
    lse_kernel<<<MB, 128>>>(out);
}